// round 7
// baseline (speedup 1.0000x reference)
#include <cuda_runtime.h>

#define BB 16
#define LTOT 128
#define LQ 32                       // L atoms per block
#define PPTOT 8192
#define NTHREADS 128
#define XCHUNKS 16                  // PPTOT / (NTHREADS*4)
#define ZSPLIT 4
#define NTILES (XCHUNKS * ZSPLIT)   // 64 partial slots per batch
#define TOTBLK (XCHUNKS * BB * ZSPLIT)  // 1024 blocks = 1 wave

__device__ float g_part[BB][4][NTILES];
__device__ unsigned int g_cnt = 0;

typedef unsigned long long f2;

__device__ __forceinline__ float rsqrt_a(float x) { float y; asm("rsqrt.approx.f32 %0,%1;" : "=f"(y) : "f"(x)); return y; }
__device__ __forceinline__ float sqrt_a(float x)  { float y; asm("sqrt.approx.f32 %0,%1;"  : "=f"(y) : "f"(x)); return y; }
__device__ __forceinline__ float rcp_a(float x)   { float y; asm("rcp.approx.f32 %0,%1;"   : "=f"(y) : "f"(x)); return y; }
__device__ __forceinline__ float ex2_a(float x)   { float y; asm("ex2.approx.f32 %0,%1;"   : "=f"(y) : "f"(x)); return y; }

__device__ __forceinline__ f2 pk(float lo, float hi) { f2 r; asm("mov.b64 %0,{%1,%2};" : "=l"(r) : "f"(lo), "f"(hi)); return r; }
__device__ __forceinline__ void upk(f2 v, float& lo, float& hi) { asm("mov.b64 {%0,%1},%2;" : "=f"(lo), "=f"(hi) : "l"(v)); }
__device__ __forceinline__ f2 fma2(f2 a, f2 b, f2 c) { f2 r; asm("fma.rn.f32x2 %0,%1,%2,%3;" : "=l"(r) : "l"(a), "l"(b), "l"(c)); return r; }
__device__ __forceinline__ f2 mul2(f2 a, f2 b) { f2 r; asm("mul.rn.f32x2 %0,%1,%2;" : "=l"(r) : "l"(a), "l"(b)); return r; }
__device__ __forceinline__ f2 add2(f2 a, f2 b) { f2 r; asm("add.rn.f32x2 %0,%1,%2;" : "=l"(r) : "l"(a), "l"(b)); return r; }

__global__ void __launch_bounds__(NTHREADS, 8) pair_kernel(
    const float* __restrict__ posL, const float* __restrict__ posP,
    const float* __restrict__ qL,   const float* __restrict__ qP,
    const float* __restrict__ xL,   const float* __restrict__ xP,
    const float* __restrict__ vdw,  const float* __restrict__ epst,
    float* __restrict__ out)
{
    // Ligand scalars, pre-duplicated; each row = 4 x 16B so LDS.128 yields 2 packed
    // operands per load. [l]: (-2x)(-2y)(-2z)(|pL|^2+1e-8)(83q)(rl)(se)(x0), dup'd
    __shared__ __align__(16) float2 sL[LQ][8];
    __shared__ float  red[4][4];
    __shared__ int    s_last;

    const int b   = blockIdx.y;
    const int tid = threadIdx.x;
    const int lbase = blockIdx.z * LQ;

    if (tid < LQ) {
        const int l = lbase + tid;
        const float* xl = xL + ((size_t)b * LTOT + l) * 9;
        float rl = 0.0f, el = 0.0f;
#pragma unroll
        for (int i = 0; i < 9; i++) {
            float v = xl[i];
            rl = fmaf(v, vdw[i],  rl);
            el = fmaf(v, epst[i], el);
        }
        el = fmaxf(el, 0.0f);
        const float* pl = posL + ((size_t)b * LTOT + l) * 3;
        float lx = pl[0], ly = pl[1], lz = pl[2];
        float sq = fmaf(lx, lx, fmaf(ly, ly, fmaf(lz, lz, 1e-8f)));
        float aw = 83.015f * qL[b * LTOT + l];
        float se = sqrt_a(el);
        sL[tid][0] = make_float2(-2.0f * lx, -2.0f * lx);
        sL[tid][1] = make_float2(-2.0f * ly, -2.0f * ly);
        sL[tid][2] = make_float2(-2.0f * lz, -2.0f * lz);
        sL[tid][3] = make_float2(sq, sq);
        sL[tid][4] = make_float2(aw, aw);
        sL[tid][5] = make_float2(rl, rl);
        sL[tid][6] = make_float2(se, se);
        sL[tid][7] = make_float2(xl[0], xl[0]);
    }
    __syncthreads();

    // --- per-thread protein atoms: 4, as two packed sets ---
    f2 ppx[2], ppy[2], ppz[2], sqp[2], qp2[2], rp2[2], sep4[2], x0p2[2];
#pragma unroll
    for (int s = 0; s < 2; s++) {
        const int p0 = blockIdx.x * (NTHREADS * 4) + s * (NTHREADS * 2) + tid;
        const int p1 = p0 + NTHREADS;
        const size_t b0 = (size_t)b * PPTOT + p0;
        const size_t b1 = (size_t)b * PPTOT + p1;
        const float* pp0 = posP + b0 * 3;
        const float* pp1 = posP + b1 * 3;
        float x0c = pp0[0], y0c = pp0[1], z0c = pp0[2];
        float x1c = pp1[0], y1c = pp1[1], z1c = pp1[2];
        ppx[s] = pk(x0c, x1c);
        ppy[s] = pk(y0c, y1c);
        ppz[s] = pk(z0c, z1c);
        sqp[s] = pk(fmaf(x0c, x0c, fmaf(y0c, y0c, z0c * z0c)),
                    fmaf(x1c, x1c, fmaf(y1c, y1c, z1c * z1c)));
        qp2[s] = pk(qP[b0], qP[b1]);
        const float* xp0 = xP + b0 * 4;
        const float* xp1 = xP + b1 * 4;
        float r0 = fmaf(xp0[0], 1.7f, fmaf(xp0[1], 1.55f, fmaf(xp0[2], 1.52f, xp0[3] * 1.8f)));
        float r1 = fmaf(xp1[0], 1.7f, fmaf(xp1[1], 1.55f, fmaf(xp1[2], 1.52f, xp1[3] * 1.8f)));
        float e0 = fmaf(xp0[0], 0.1f, fmaf(xp0[1], 0.1f, fmaf(xp0[2], 0.15f, xp0[3] * 0.2f)));
        float e1 = fmaf(xp1[0], 0.1f, fmaf(xp1[1], 0.1f, fmaf(xp1[2], 0.15f, xp1[3] * 0.2f)));
        rp2[s]  = pk(r0, r1);
        sep4[s] = pk(4.0f * sqrt_a(e0), 4.0f * sqrt_a(e1));
        x0p2[s] = pk(xp0[0], xp1[0]);
    }

    // packed constants (tanh poly in u = eer^2: ee = eer + (eer*u)*(c1 + c2*u))
    const f2 C_U1   = pk(-8.3333333e-6f, -8.3333333e-6f);
    const f2 C_U2   = pk(8.3333333e-11f, 8.3333333e-11f);
    const f2 C_NEG1 = pk(-1.0f, -1.0f);
    const f2 C_K1   = pk(2.8853900817779268f, 2.8853900817779268f);
    const f2 C_K0   = pk(-34.624680981335124f, -34.624680981335124f);
    const f2 C_256  = pk(256.0f, 256.0f);

    f2 acc_l = 0ull, acc_d = 0ull;
    f2 acc_h[2] = {0ull, 0ull};
    float accp0 = 0.0f, accp1 = 0.0f;

#pragma unroll 8
    for (int l = 0; l < LQ; l++) {
        const ulonglong2* slv = (const ulonglong2*)sL[l];
        ulonglong2 v01 = slv[0];   // (-2x) (-2y)
        ulonglong2 v23 = slv[1];   // (-2z) (sql)
        ulonglong2 v45 = slv[2];   // (aw)  (rl)
        ulonglong2 v67 = slv[3];   // (se)  (x0)

#pragma unroll
        for (int s = 0; s < 2; s++) {
            // d2 = |pL|^2 + |pP|^2 - 2 pL.pP  (+1e-8 folded into sql)
            f2 ssum = add2(v23.y, sqp[s]);
            f2 d2 = fma2(v01.x, ppx[s], fma2(v01.y, ppy[s], fma2(v23.x, ppz[s], ssum)));
            f2 sig  = add2(v45.y, rp2[s]);
            f2 s2   = fma2(sig, add2(sig, sig), d2);
            float s2l, s2h; upk(s2, s2l, s2h);
            f2 isd = pk(rsqrt_a(s2l), rsqrt_a(s2h));               // 1/soft_dist

            // e_elec = 200*tanh(eer/200): ee = eer + (eer*u)*(c1 + c2*u), u=eer^2
            f2 eer = mul2(mul2(v45.x, qp2[s]), isd);
            f2 u   = mul2(eer, eer);
            f2 m   = mul2(eer, u);
            f2 t   = fma2(u, C_U2, C_U1);
            f2 ee  = fma2(m, t, eer);

            // LJ soft-core (always <= 0): evr = ce * r6 * (r6 - 1)
            f2 rat = mul2(sig, isd);
            f2 r2 = mul2(rat, rat);
            f2 r6 = mul2(mul2(r2, r2), r2);
            f2 ce = mul2(v67.x, sep4[s]);
            f2 evr = mul2(mul2(ce, r6), add2(r6, C_NEG1));
            f2 e3  = mul2(mul2(evr, evr), evr);
            f2 suml = add2(ee, evr);                   // log branch (clamp = identity)

            float d2l, d2h; upk(d2, d2l, d2h);
            float dl = sqrt_a(d2l), dh = sqrt_a(d2h);

            // mask fused with hsa reciprocal: rab = 1/((1+ex)*(d^4+256))
            f2 xg = fma2(pk(dl, dh), C_K1, C_K0);
            float xal, xah; upk(xg, xal, xah);
            f2 ex = pk(ex2_a(xal), ex2_a(xah));
            f2 hd = fma2(d2, d2, C_256);
            f2 ab = fma2(ex, hd, hd);
            float abl, abh; upk(ab, abl, abh);
            f2 rab  = pk(rcp_a(abl), rcp_a(abh));
            f2 mk = mul2(hd, rab);

            acc_h[s] = fma2(v67.y, rab, acc_h[s]);     // x0p factored out post-loop
            acc_l = fma2(suml, mk, acc_l);
            acc_d = fma2(e3, mk, acc_d);               // soft = log - acc_d/300

            // pauli (scalar; FMNMX on alu pipe)
            float sgl, sgh; upk(sig, sgl, sgh);
            float ov0 = fmaxf(fmaf(sgl, 0.6f, -dl), 0.0f);
            float ov1 = fmaxf(fmaf(sgh, 0.6f, -dh), 0.0f);
            accp0 = fmaf(ov0, ov0, accp0);
            accp1 = fmaf(ov1, ov1, accp1);
        }
    }

    acc_h[0] = mul2(acc_h[0], x0p2[0]);   // deferred x_P[0] factors
    acc_h[1] = mul2(acc_h[1], x0p2[1]);

    // --- block reduction ---
    float v1l, v1h, vdl, vdh, h0l, h0h, h1l, h1h;
    upk(acc_l, v1l, v1h);
    upk(acc_d, vdl, vdh);
    upk(acc_h[0], h0l, h0h);
    upk(acc_h[1], h1l, h1h);
    float v1 = v1l + v1h;
    float v0 = fmaf(vdl + vdh, -3.3333333333e-3f, v1);   // soft sum
    float v2 = (h0l + h0h) + (h1l + h1h);
    float v3 = accp0 + accp1;
#pragma unroll
    for (int off = 16; off > 0; off >>= 1) {
        v0 += __shfl_xor_sync(0xFFFFFFFFu, v0, off);
        v1 += __shfl_xor_sync(0xFFFFFFFFu, v1, off);
        v2 += __shfl_xor_sync(0xFFFFFFFFu, v2, off);
        v3 += __shfl_xor_sync(0xFFFFFFFFu, v3, off);
    }
    const int wid = tid >> 5;
    if ((tid & 31) == 0) {
        red[wid][0] = v0; red[wid][1] = v1; red[wid][2] = v2; red[wid][3] = v3;
    }
    __syncthreads();
    const int slot = blockIdx.z * XCHUNKS + blockIdx.x;
    if (tid < 4) {
        float s = red[0][tid] + red[1][tid] + red[2][tid] + red[3][tid];
        g_part[b][tid][slot] = s;
    }
    __threadfence();
    if (tid == 0) {
        unsigned int old = atomicAdd(&g_cnt, 1u);
        s_last = (old == TOTBLK - 1) ? 1 : 0;
    }
    __syncthreads();
    if (!s_last) return;

    // --- last block: final reduction + epilogue ---
    __threadfence();
    __shared__ float fin[BB][4];
    {
        const int slot2 = tid >> 1;           // 0..63  (16 batches x 4 comps)
        const int half  = tid & 1;
        const int fb = slot2 >> 2, fc = slot2 & 3;
        float s = 0.0f;
#pragma unroll 8
        for (int i = half * (NTILES / 2); i < (half + 1) * (NTILES / 2); i++)
            s += g_part[fb][fc][i];
        s += __shfl_xor_sync(0xFFFFFFFFu, s, 1);
        if (half == 0) fin[fb][fc] = s;
    }
    __syncthreads();
    if (tid < BB) {
        float s  = fin[tid][0];
        float lg = fin[tid][1];
        float h  = fin[tid][2];
        float pa = fin[tid][3];

        float e_hsa   = -0.5f * 256.0f * h;
        float e_pauli = 95.257412682243336f * pa;   // sigmoid(3.0)*100

        float e_raw  = s + 5.0f * e_hsa + e_pauli;
        float e_hard = fminf(e_pauli, 10000.0f);
        float e_soft_log = fminf(fmaxf(lg + 5.0f * e_hsa, -500.0f), 5000.0f);
        float loge = fminf(e_soft_log + e_hard, 1000000.0f);

        out[tid]      = e_raw;
        out[16 + tid] = e_hard;
        out[33 + tid] = loge;
    }
    if (tid == 0) {
        out[32] = 2.0f;   // ALPHA
        g_cnt = 0;        // reset for next graph replay (deterministic)
    }
}

extern "C" void kernel_launch(void* const* d_in, const int* in_sizes, int n_in,
                              void* d_out, int out_size) {
    const float* posL = (const float*)d_in[0];
    const float* posP = (const float*)d_in[1];
    const float* qL   = (const float*)d_in[2];
    const float* qP   = (const float*)d_in[3];
    const float* xL   = (const float*)d_in[4];
    const float* xP   = (const float*)d_in[5];
    const float* vdw  = (const float*)d_in[6];
    const float* epst = (const float*)d_in[7];
    float* out = (float*)d_out;

    dim3 grid(XCHUNKS, BB, ZSPLIT);
    pair_kernel<<<grid, NTHREADS>>>(posL, posP, qL, qP, xL, xP, vdw, epst, out);
}

// round 12
// speedup vs baseline: 1.0528x; 1.0528x over previous
#include <cuda_runtime.h>

#define BB 16
#define LTOT 128
#define LQ 32                       // L atoms per block
#define PPTOT 8192
#define NTHREADS 128
#define XCHUNKS 16                  // PPTOT / (NTHREADS*4)
#define ZSPLIT 4
#define NTILES (XCHUNKS * ZSPLIT)   // 64 partial slots per batch
#define TOTBLK (XCHUNKS * BB * ZSPLIT)  // 1024 blocks = 1 wave @ 7 blocks/SM

__device__ float g_part[BB][4][NTILES];
__device__ unsigned int g_cnt = 0;

typedef unsigned long long f2;

__device__ __forceinline__ float rsqrt_a(float x) { float y; asm("rsqrt.approx.f32 %0,%1;" : "=f"(y) : "f"(x)); return y; }
__device__ __forceinline__ float sqrt_a(float x)  { float y; asm("sqrt.approx.f32 %0,%1;"  : "=f"(y) : "f"(x)); return y; }
__device__ __forceinline__ float rcp_a(float x)   { float y; asm("rcp.approx.f32 %0,%1;"   : "=f"(y) : "f"(x)); return y; }
__device__ __forceinline__ float ex2_a(float x)   { float y; asm("ex2.approx.f32 %0,%1;"   : "=f"(y) : "f"(x)); return y; }

__device__ __forceinline__ f2 pk(float lo, float hi) { f2 r; asm("mov.b64 %0,{%1,%2};" : "=l"(r) : "f"(lo), "f"(hi)); return r; }
__device__ __forceinline__ void upk(f2 v, float& lo, float& hi) { asm("mov.b64 {%0,%1},%2;" : "=f"(lo), "=f"(hi) : "l"(v)); }
__device__ __forceinline__ f2 fma2(f2 a, f2 b, f2 c) { f2 r; asm("fma.rn.f32x2 %0,%1,%2,%3;" : "=l"(r) : "l"(a), "l"(b), "l"(c)); return r; }
__device__ __forceinline__ f2 mul2(f2 a, f2 b) { f2 r; asm("mul.rn.f32x2 %0,%1,%2;" : "=l"(r) : "l"(a), "l"(b)); return r; }
__device__ __forceinline__ f2 add2(f2 a, f2 b) { f2 r; asm("add.rn.f32x2 %0,%1,%2;" : "=l"(r) : "l"(a), "l"(b)); return r; }

__global__ void __launch_bounds__(NTHREADS, 7) pair_kernel(
    const float* __restrict__ posL, const float* __restrict__ posP,
    const float* __restrict__ qL,   const float* __restrict__ qP,
    const float* __restrict__ xL,   const float* __restrict__ xP,
    const float* __restrict__ vdw,  const float* __restrict__ epst,
    float* __restrict__ out)
{
    // Ligand scalars, pre-duplicated; each row = 4 x 16B so LDS.128 yields 2 packed
    // operands per load. [l]: (-2x)(-2y)(-2z)(|pL|^2+1e-8)(83q)(rl)(se)(x0), dup'd
    __shared__ __align__(16) float2 sL[LQ][8];
    __shared__ float  red[4][4];
    __shared__ int    s_last;

    const int b   = blockIdx.y;
    const int tid = threadIdx.x;
    const int lbase = blockIdx.z * LQ;

    if (tid < LQ) {
        const int l = lbase + tid;
        const float* xl = xL + ((size_t)b * LTOT + l) * 9;
        float rl = 0.0f, el = 0.0f;
#pragma unroll
        for (int i = 0; i < 9; i++) {
            float v = xl[i];
            rl = fmaf(v, vdw[i],  rl);
            el = fmaf(v, epst[i], el);
        }
        el = fmaxf(el, 0.0f);
        const float* pl = posL + ((size_t)b * LTOT + l) * 3;
        float lx = pl[0], ly = pl[1], lz = pl[2];
        float sq = fmaf(lx, lx, fmaf(ly, ly, fmaf(lz, lz, 1e-8f)));
        float aw = 83.015f * qL[b * LTOT + l];
        float se = sqrt_a(el);
        sL[tid][0] = make_float2(-2.0f * lx, -2.0f * lx);
        sL[tid][1] = make_float2(-2.0f * ly, -2.0f * ly);
        sL[tid][2] = make_float2(-2.0f * lz, -2.0f * lz);
        sL[tid][3] = make_float2(sq, sq);
        sL[tid][4] = make_float2(aw, aw);
        sL[tid][5] = make_float2(rl, rl);
        sL[tid][6] = make_float2(se, se);
        sL[tid][7] = make_float2(xl[0], xl[0]);
    }
    __syncthreads();

    // --- per-thread protein atoms: 4, as two packed sets ---
    f2 ppx[2], ppy[2], ppz[2], sqp[2], qp2[2], rp2[2], sep4[2], x0p2[2];
#pragma unroll
    for (int s = 0; s < 2; s++) {
        const int p0 = blockIdx.x * (NTHREADS * 4) + s * (NTHREADS * 2) + tid;
        const int p1 = p0 + NTHREADS;
        const size_t b0 = (size_t)b * PPTOT + p0;
        const size_t b1 = (size_t)b * PPTOT + p1;
        const float* pp0 = posP + b0 * 3;
        const float* pp1 = posP + b1 * 3;
        float x0c = pp0[0], y0c = pp0[1], z0c = pp0[2];
        float x1c = pp1[0], y1c = pp1[1], z1c = pp1[2];
        ppx[s] = pk(x0c, x1c);
        ppy[s] = pk(y0c, y1c);
        ppz[s] = pk(z0c, z1c);
        sqp[s] = pk(fmaf(x0c, x0c, fmaf(y0c, y0c, z0c * z0c)),
                    fmaf(x1c, x1c, fmaf(y1c, y1c, z1c * z1c)));
        qp2[s] = pk(qP[b0], qP[b1]);
        const float* xp0 = xP + b0 * 4;
        const float* xp1 = xP + b1 * 4;
        float r0 = fmaf(xp0[0], 1.7f, fmaf(xp0[1], 1.55f, fmaf(xp0[2], 1.52f, xp0[3] * 1.8f)));
        float r1 = fmaf(xp1[0], 1.7f, fmaf(xp1[1], 1.55f, fmaf(xp1[2], 1.52f, xp1[3] * 1.8f)));
        float e0 = fmaf(xp0[0], 0.1f, fmaf(xp0[1], 0.1f, fmaf(xp0[2], 0.15f, xp0[3] * 0.2f)));
        float e1 = fmaf(xp1[0], 0.1f, fmaf(xp1[1], 0.1f, fmaf(xp1[2], 0.15f, xp1[3] * 0.2f)));
        rp2[s]  = pk(r0, r1);
        sep4[s] = pk(4.0f * sqrt_a(e0), 4.0f * sqrt_a(e1));
        x0p2[s] = pk(xp0[0], xp1[0]);
    }

    // packed constants (tanh poly in u = eer^2: ee = eer + (eer*u)*(c1 + c2*u))
    const f2 C_U1   = pk(-8.3333333e-6f, -8.3333333e-6f);
    const f2 C_U2   = pk(8.3333333e-11f, 8.3333333e-11f);
    const f2 C_NEG1 = pk(-1.0f, -1.0f);
    const f2 C_K1   = pk(2.8853900817779268f, 2.8853900817779268f);
    const f2 C_K0   = pk(-34.624680981335124f, -34.624680981335124f);
    const f2 C_256  = pk(256.0f, 256.0f);

    f2 acc_l = 0ull, acc_d = 0ull;
    f2 acc_h[2] = {0ull, 0ull};
    float accp0 = 0.0f, accp1 = 0.0f;

#pragma unroll 8
    for (int l = 0; l < LQ; l++) {
        const ulonglong2* slv = (const ulonglong2*)sL[l];
        ulonglong2 v01 = slv[0];   // (-2x) (-2y)
        ulonglong2 v23 = slv[1];   // (-2z) (sql)
        ulonglong2 v45 = slv[2];   // (aw)  (rl)
        ulonglong2 v67 = slv[3];   // (se)  (x0)

#pragma unroll
        for (int s = 0; s < 2; s++) {
            // d2 = |pL|^2 + |pP|^2 - 2 pL.pP  (+1e-8 folded into sql)
            f2 ssum = add2(v23.y, sqp[s]);
            f2 d2 = fma2(v01.x, ppx[s], fma2(v01.y, ppy[s], fma2(v23.x, ppz[s], ssum)));
            f2 sig  = add2(v45.y, rp2[s]);
            f2 s2   = fma2(sig, add2(sig, sig), d2);
            float s2l, s2h; upk(s2, s2l, s2h);
            f2 isd = pk(rsqrt_a(s2l), rsqrt_a(s2h));               // 1/soft_dist

            // e_elec = 200*tanh(eer/200): ee = eer + (eer*u)*(c1 + c2*u), u=eer^2
            f2 eer = mul2(mul2(v45.x, qp2[s]), isd);
            f2 u   = mul2(eer, eer);
            f2 m   = mul2(eer, u);
            f2 t   = fma2(u, C_U2, C_U1);
            f2 ee  = fma2(m, t, eer);

            // LJ soft-core (always <= 0): evr = ce * r6 * (r6 - 1)
            f2 rat = mul2(sig, isd);
            f2 r2 = mul2(rat, rat);
            f2 r6 = mul2(mul2(r2, r2), r2);
            f2 ce = mul2(v67.x, sep4[s]);
            f2 evr = mul2(mul2(ce, r6), add2(r6, C_NEG1));
            f2 e3  = mul2(mul2(evr, evr), evr);
            f2 suml = add2(ee, evr);                   // log branch (clamp = identity)

            float d2l, d2h; upk(d2, d2l, d2h);
            float dl = sqrt_a(d2l), dh = sqrt_a(d2h);

            // mask fused with hsa reciprocal: rab = 1/((1+ex)*(d^4+256))
            f2 xg = fma2(pk(dl, dh), C_K1, C_K0);
            float xal, xah; upk(xg, xal, xah);
            f2 ex = pk(ex2_a(xal), ex2_a(xah));
            f2 hd = fma2(d2, d2, C_256);
            f2 ab = fma2(ex, hd, hd);
            float abl, abh; upk(ab, abl, abh);
            f2 rab  = pk(rcp_a(abl), rcp_a(abh));
            f2 mk = mul2(hd, rab);

            acc_h[s] = fma2(v67.y, rab, acc_h[s]);     // x0p factored out post-loop
            acc_l = fma2(suml, mk, acc_l);
            acc_d = fma2(e3, mk, acc_d);               // soft = log - acc_d/300

            // pauli (scalar; FMNMX on alu pipe)
            float sgl, sgh; upk(sig, sgl, sgh);
            float ov0 = fmaxf(fmaf(sgl, 0.6f, -dl), 0.0f);
            float ov1 = fmaxf(fmaf(sgh, 0.6f, -dh), 0.0f);
            accp0 = fmaf(ov0, ov0, accp0);
            accp1 = fmaf(ov1, ov1, accp1);
        }
    }

    acc_h[0] = mul2(acc_h[0], x0p2[0]);   // deferred x_P[0] factors
    acc_h[1] = mul2(acc_h[1], x0p2[1]);

    // --- block reduction ---
    float v1l, v1h, vdl, vdh, h0l, h0h, h1l, h1h;
    upk(acc_l, v1l, v1h);
    upk(acc_d, vdl, vdh);
    upk(acc_h[0], h0l, h0h);
    upk(acc_h[1], h1l, h1h);
    float v1 = v1l + v1h;
    float v0 = fmaf(vdl + vdh, -3.3333333333e-3f, v1);   // soft sum
    float v2 = (h0l + h0h) + (h1l + h1h);
    float v3 = accp0 + accp1;
#pragma unroll
    for (int off = 16; off > 0; off >>= 1) {
        v0 += __shfl_xor_sync(0xFFFFFFFFu, v0, off);
        v1 += __shfl_xor_sync(0xFFFFFFFFu, v1, off);
        v2 += __shfl_xor_sync(0xFFFFFFFFu, v2, off);
        v3 += __shfl_xor_sync(0xFFFFFFFFu, v3, off);
    }
    const int wid = tid >> 5;
    if ((tid & 31) == 0) {
        red[wid][0] = v0; red[wid][1] = v1; red[wid][2] = v2; red[wid][3] = v3;
    }
    __syncthreads();
    const int slot = blockIdx.z * XCHUNKS + blockIdx.x;
    if (tid < 4) {
        float s = red[0][tid] + red[1][tid] + red[2][tid] + red[3][tid];
        g_part[b][tid][slot] = s;
    }
    __threadfence();
    if (tid == 0) {
        unsigned int old = atomicAdd(&g_cnt, 1u);
        s_last = (old == TOTBLK - 1) ? 1 : 0;
    }
    __syncthreads();
    if (!s_last) return;

    // --- last block: final reduction + epilogue ---
    __threadfence();
    __shared__ float fin[BB][4];
    {
        const int slot2 = tid >> 1;           // 0..63  (16 batches x 4 comps)
        const int half  = tid & 1;
        const int fb = slot2 >> 2, fc = slot2 & 3;
        float s = 0.0f;
#pragma unroll 8
        for (int i = half * (NTILES / 2); i < (half + 1) * (NTILES / 2); i++)
            s += g_part[fb][fc][i];
        s += __shfl_xor_sync(0xFFFFFFFFu, s, 1);
        if (half == 0) fin[fb][fc] = s;
    }
    __syncthreads();
    if (tid < BB) {
        float s  = fin[tid][0];
        float lg = fin[tid][1];
        float h  = fin[tid][2];
        float pa = fin[tid][3];

        float e_hsa   = -0.5f * 256.0f * h;
        float e_pauli = 95.257412682243336f * pa;   // sigmoid(3.0)*100

        float e_raw  = s + 5.0f * e_hsa + e_pauli;
        float e_hard = fminf(e_pauli, 10000.0f);
        float e_soft_log = fminf(fmaxf(lg + 5.0f * e_hsa, -500.0f), 5000.0f);
        float loge = fminf(e_soft_log + e_hard, 1000000.0f);

        out[tid]      = e_raw;
        out[16 + tid] = e_hard;
        out[33 + tid] = loge;
    }
    if (tid == 0) {
        out[32] = 2.0f;   // ALPHA
        g_cnt = 0;        // reset for next graph replay (deterministic)
    }
}

extern "C" void kernel_launch(void* const* d_in, const int* in_sizes, int n_in,
                              void* d_out, int out_size) {
    const float* posL = (const float*)d_in[0];
    const float* posP = (const float*)d_in[1];
    const float* qL   = (const float*)d_in[2];
    const float* qP   = (const float*)d_in[3];
    const float* xL   = (const float*)d_in[4];
    const float* xP   = (const float*)d_in[5];
    const float* vdw  = (const float*)d_in[6];
    const float* epst = (const float*)d_in[7];
    float* out = (float*)d_out;

    dim3 grid(XCHUNKS, BB, ZSPLIT);
    pair_kernel<<<grid, NTHREADS>>>(posL, posP, qL, qP, xL, xP, vdw, epst, out);
}

// round 14
// speedup vs baseline: 1.1020x; 1.0468x over previous
#include <cuda_runtime.h>

#define BB 16
#define LTOT 128
#define LQ 32                       // L atoms per block
#define PPTOT 8192
#define NTHREADS 128
#define XCHUNKS 16                  // PPTOT / (NTHREADS*4)
#define ZSPLIT 4
#define NTILES (XCHUNKS * ZSPLIT)   // 64 partial slots per batch
#define TOTBLK (XCHUNKS * BB * ZSPLIT)  // 1024 blocks = 1 wave @ 7 blocks/SM

__device__ float g_part[BB][4][NTILES];
__device__ unsigned int g_cnt = 0;

typedef unsigned long long f2;

__device__ __forceinline__ float rsqrt_a(float x) { float y; asm("rsqrt.approx.f32 %0,%1;" : "=f"(y) : "f"(x)); return y; }
__device__ __forceinline__ float sqrt_a(float x)  { float y; asm("sqrt.approx.f32 %0,%1;"  : "=f"(y) : "f"(x)); return y; }
__device__ __forceinline__ float rcp_a(float x)   { float y; asm("rcp.approx.f32 %0,%1;"   : "=f"(y) : "f"(x)); return y; }
__device__ __forceinline__ float tanh_a(float x)  { float y; asm("tanh.approx.f32 %0,%1;"  : "=f"(y) : "f"(x)); return y; }

__device__ __forceinline__ f2 pk(float lo, float hi) { f2 r; asm("mov.b64 %0,{%1,%2};" : "=l"(r) : "f"(lo), "f"(hi)); return r; }
__device__ __forceinline__ void upk(f2 v, float& lo, float& hi) { asm("mov.b64 {%0,%1},%2;" : "=f"(lo), "=f"(hi) : "l"(v)); }
__device__ __forceinline__ f2 fma2(f2 a, f2 b, f2 c) { f2 r; asm("fma.rn.f32x2 %0,%1,%2,%3;" : "=l"(r) : "l"(a), "l"(b), "l"(c)); return r; }
__device__ __forceinline__ f2 mul2(f2 a, f2 b) { f2 r; asm("mul.rn.f32x2 %0,%1,%2;" : "=l"(r) : "l"(a), "l"(b)); return r; }
__device__ __forceinline__ f2 add2(f2 a, f2 b) { f2 r; asm("add.rn.f32x2 %0,%1,%2;" : "=l"(r) : "l"(a), "l"(b)); return r; }

__global__ void __launch_bounds__(NTHREADS, 7) pair_kernel(
    const float* __restrict__ posL, const float* __restrict__ posP,
    const float* __restrict__ qL,   const float* __restrict__ qP,
    const float* __restrict__ xL,   const float* __restrict__ xP,
    const float* __restrict__ vdw,  const float* __restrict__ epst,
    float* __restrict__ out)
{
    // Ligand scalars, pre-duplicated; each row = 4 x 16B so LDS.128 yields 2 packed
    // operands per load. [l]: (-2x)(-2y)(-2z)(|pL|^2+1e-8)(83q)(rl)(se)(x0), dup'd
    __shared__ __align__(16) float2 sL[LQ][8];
    __shared__ float  red[4][4];
    __shared__ int    s_last;

    const int b   = blockIdx.y;
    const int tid = threadIdx.x;
    const int lbase = blockIdx.z * LQ;

    if (tid < LQ) {
        const int l = lbase + tid;
        const float* xl = xL + ((size_t)b * LTOT + l) * 9;
        float rl = 0.0f, el = 0.0f;
#pragma unroll
        for (int i = 0; i < 9; i++) {
            float v = xl[i];
            rl = fmaf(v, vdw[i],  rl);
            el = fmaf(v, epst[i], el);
        }
        el = fmaxf(el, 0.0f);
        const float* pl = posL + ((size_t)b * LTOT + l) * 3;
        float lx = pl[0], ly = pl[1], lz = pl[2];
        float sq = fmaf(lx, lx, fmaf(ly, ly, fmaf(lz, lz, 1e-8f)));
        float aw = 83.015f * qL[b * LTOT + l];
        float se = sqrt_a(el);
        sL[tid][0] = make_float2(-2.0f * lx, -2.0f * lx);
        sL[tid][1] = make_float2(-2.0f * ly, -2.0f * ly);
        sL[tid][2] = make_float2(-2.0f * lz, -2.0f * lz);
        sL[tid][3] = make_float2(sq, sq);
        sL[tid][4] = make_float2(aw, aw);
        sL[tid][5] = make_float2(rl, rl);
        sL[tid][6] = make_float2(se, se);
        sL[tid][7] = make_float2(xl[0], xl[0]);
    }
    __syncthreads();

    // --- per-thread protein atoms: 4, as two packed sets ---
    f2 ppx[2], ppy[2], ppz[2], sqp[2], qp2[2], rp2[2], sep4[2], x0p2[2];
#pragma unroll
    for (int s = 0; s < 2; s++) {
        const int p0 = blockIdx.x * (NTHREADS * 4) + s * (NTHREADS * 2) + tid;
        const int p1 = p0 + NTHREADS;
        const size_t b0 = (size_t)b * PPTOT + p0;
        const size_t b1 = (size_t)b * PPTOT + p1;
        const float* pp0 = posP + b0 * 3;
        const float* pp1 = posP + b1 * 3;
        float x0c = pp0[0], y0c = pp0[1], z0c = pp0[2];
        float x1c = pp1[0], y1c = pp1[1], z1c = pp1[2];
        ppx[s] = pk(x0c, x1c);
        ppy[s] = pk(y0c, y1c);
        ppz[s] = pk(z0c, z1c);
        sqp[s] = pk(fmaf(x0c, x0c, fmaf(y0c, y0c, z0c * z0c)),
                    fmaf(x1c, x1c, fmaf(y1c, y1c, z1c * z1c)));
        qp2[s] = pk(qP[b0], qP[b1]);
        const float* xp0 = xP + b0 * 4;
        const float* xp1 = xP + b1 * 4;
        float r0 = fmaf(xp0[0], 1.7f, fmaf(xp0[1], 1.55f, fmaf(xp0[2], 1.52f, xp0[3] * 1.8f)));
        float r1 = fmaf(xp1[0], 1.7f, fmaf(xp1[1], 1.55f, fmaf(xp1[2], 1.52f, xp1[3] * 1.8f)));
        float e0 = fmaf(xp0[0], 0.1f, fmaf(xp0[1], 0.1f, fmaf(xp0[2], 0.15f, xp0[3] * 0.2f)));
        float e1 = fmaf(xp1[0], 0.1f, fmaf(xp1[1], 0.1f, fmaf(xp1[2], 0.15f, xp1[3] * 0.2f)));
        rp2[s]  = pk(r0, r1);
        sep4[s] = pk(4.0f * sqrt_a(e0), 4.0f * sqrt_a(e1));
        x0p2[s] = pk(xp0[0], xp1[0]);
    }

    // packed constants (tanh poly in u = eer^2: ee = eer + (eer*u)*(c1 + c2*u))
    const f2 C_U1   = pk(-8.3333333e-6f, -8.3333333e-6f);
    const f2 C_U2   = pk(8.3333333e-11f, 8.3333333e-11f);
    const f2 C_NEG1 = pk(-1.0f, -1.0f);
    const f2 C_HALF = pk(0.5f, 0.5f);
    const f2 C_256  = pk(256.0f, 256.0f);

    f2 acc_l = 0ull, acc_d = 0ull;
    f2 acc_h[2] = {0ull, 0ull};
    float accp0 = 0.0f, accp1 = 0.0f;

#pragma unroll 8
    for (int l = 0; l < LQ; l++) {
        const ulonglong2* slv = (const ulonglong2*)sL[l];
        ulonglong2 v01 = slv[0];   // (-2x) (-2y)
        ulonglong2 v23 = slv[1];   // (-2z) (sql)
        ulonglong2 v45 = slv[2];   // (aw)  (rl)
        ulonglong2 v67 = slv[3];   // (se)  (x0)

#pragma unroll
        for (int s = 0; s < 2; s++) {
            // d2 = |pL|^2 + |pP|^2 - 2 pL.pP  (+1e-8 folded into sql)
            f2 ssum = add2(v23.y, sqp[s]);
            f2 d2 = fma2(v01.x, ppx[s], fma2(v01.y, ppy[s], fma2(v23.x, ppz[s], ssum)));
            f2 sig  = add2(v45.y, rp2[s]);
            f2 s2   = fma2(sig, add2(sig, sig), d2);
            float s2l, s2h; upk(s2, s2l, s2h);
            f2 isd = pk(rsqrt_a(s2l), rsqrt_a(s2h));               // 1/soft_dist

            // hsa reciprocal, independent of sqrt chain: rcph = 1/(d2^2 + 256)
            f2 hd = fma2(d2, d2, C_256);
            float hdl, hdh; upk(hd, hdl, hdh);
            f2 rcph = pk(rcp_a(hdl), rcp_a(hdh));

            // dist + mask via tanh: mask = 0.5 + 0.5*tanh(12 - d)
            float d2l, d2h; upk(d2, d2l, d2h);
            float dl = sqrt_a(d2l), dh = sqrt_a(d2h);
            float thl = tanh_a(12.0f - dl);
            float thh = tanh_a(12.0f - dh);
            f2 mask = fma2(pk(thl, thh), C_HALF, C_HALF);

            // e_elec = 200*tanh(eer/200): ee = eer + (eer*u)*(c1 + c2*u), u=eer^2
            f2 eer = mul2(mul2(v45.x, qp2[s]), isd);
            f2 u   = mul2(eer, eer);
            f2 m   = mul2(eer, u);
            f2 t   = fma2(u, C_U2, C_U1);
            f2 ee  = fma2(m, t, eer);

            // LJ soft-core (always <= 0): evr = ce * r6 * (r6 - 1)
            f2 rat = mul2(sig, isd);
            f2 r2 = mul2(rat, rat);
            f2 r6 = mul2(mul2(r2, r2), r2);
            f2 ce = mul2(v67.x, sep4[s]);
            f2 evr = mul2(mul2(ce, r6), add2(r6, C_NEG1));
            f2 e3  = mul2(mul2(evr, evr), evr);
            f2 suml = add2(ee, evr);                   // log branch (clamp = identity)

            // accumulate
            f2 rhm = mul2(rcph, mask);                 // = mask/(d^4+256); x256 in epilogue
            acc_h[s] = fma2(v67.y, rhm, acc_h[s]);     // x0p factored out post-loop
            acc_l = fma2(suml, mask, acc_l);
            acc_d = fma2(e3, mask, acc_d);             // soft = log - acc_d/300

            // pauli (scalar; FMNMX on alu pipe)
            float sgl, sgh; upk(sig, sgl, sgh);
            float ov0 = fmaxf(fmaf(sgl, 0.6f, -dl), 0.0f);
            float ov1 = fmaxf(fmaf(sgh, 0.6f, -dh), 0.0f);
            accp0 = fmaf(ov0, ov0, accp0);
            accp1 = fmaf(ov1, ov1, accp1);
        }
    }

    acc_h[0] = mul2(acc_h[0], x0p2[0]);   // deferred x_P[0] factors
    acc_h[1] = mul2(acc_h[1], x0p2[1]);

    // --- block reduction ---
    float v1l, v1h, vdl, vdh, h0l, h0h, h1l, h1h;
    upk(acc_l, v1l, v1h);
    upk(acc_d, vdl, vdh);
    upk(acc_h[0], h0l, h0h);
    upk(acc_h[1], h1l, h1h);
    float v1 = v1l + v1h;
    float v0 = fmaf(vdl + vdh, -3.3333333333e-3f, v1);   // soft sum
    float v2 = (h0l + h0h) + (h1l + h1h);
    float v3 = accp0 + accp1;
#pragma unroll
    for (int off = 16; off > 0; off >>= 1) {
        v0 += __shfl_xor_sync(0xFFFFFFFFu, v0, off);
        v1 += __shfl_xor_sync(0xFFFFFFFFu, v1, off);
        v2 += __shfl_xor_sync(0xFFFFFFFFu, v2, off);
        v3 += __shfl_xor_sync(0xFFFFFFFFu, v3, off);
    }
    const int wid = tid >> 5;
    if ((tid & 31) == 0) {
        red[wid][0] = v0; red[wid][1] = v1; red[wid][2] = v2; red[wid][3] = v3;
    }
    __syncthreads();
    const int slot = blockIdx.z * XCHUNKS + blockIdx.x;
    if (tid < 4) {
        float s = red[0][tid] + red[1][tid] + red[2][tid] + red[3][tid];
        g_part[b][tid][slot] = s;
    }
    __threadfence();
    if (tid == 0) {
        unsigned int old = atomicAdd(&g_cnt, 1u);
        s_last = (old == TOTBLK - 1) ? 1 : 0;
    }
    __syncthreads();
    if (!s_last) return;

    // --- last block: final reduction + epilogue ---
    __threadfence();
    __shared__ float fin[BB][4];
    {
        const int slot2 = tid >> 1;           // 0..63  (16 batches x 4 comps)
        const int half  = tid & 1;
        const int fb = slot2 >> 2, fc = slot2 & 3;
        float s = 0.0f;
#pragma unroll 8
        for (int i = half * (NTILES / 2); i < (half + 1) * (NTILES / 2); i++)
            s += g_part[fb][fc][i];
        s += __shfl_xor_sync(0xFFFFFFFFu, s, 1);
        if (half == 0) fin[fb][fc] = s;
    }
    __syncthreads();
    if (tid < BB) {
        float s  = fin[tid][0];
        float lg = fin[tid][1];
        float h  = fin[tid][2];
        float pa = fin[tid][3];

        float e_hsa   = -0.5f * 256.0f * h;
        float e_pauli = 95.257412682243336f * pa;   // sigmoid(3.0)*100

        float e_raw  = s + 5.0f * e_hsa + e_pauli;
        float e_hard = fminf(e_pauli, 10000.0f);
        float e_soft_log = fminf(fmaxf(lg + 5.0f * e_hsa, -500.0f), 5000.0f);
        float loge = fminf(e_soft_log + e_hard, 1000000.0f);

        out[tid]      = e_raw;
        out[16 + tid] = e_hard;
        out[33 + tid] = loge;
    }
    if (tid == 0) {
        out[32] = 2.0f;   // ALPHA
        g_cnt = 0;        // reset for next graph replay (deterministic)
    }
}

extern "C" void kernel_launch(void* const* d_in, const int* in_sizes, int n_in,
                              void* d_out, int out_size) {
    const float* posL = (const float*)d_in[0];
    const float* posP = (const float*)d_in[1];
    const float* qL   = (const float*)d_in[2];
    const float* qP   = (const float*)d_in[3];
    const float* xL   = (const float*)d_in[4];
    const float* xP   = (const float*)d_in[5];
    const float* vdw  = (const float*)d_in[6];
    const float* epst = (const float*)d_in[7];
    float* out = (float*)d_out;

    dim3 grid(XCHUNKS, BB, ZSPLIT);
    pair_kernel<<<grid, NTHREADS>>>(posL, posP, qL, qP, xL, xP, vdw, epst, out);
}

// round 16
// speedup vs baseline: 1.1750x; 1.0662x over previous
#include <cuda_runtime.h>

#define BB 16
#define LTOT 128
#define LQ 32                       // L atoms per block
#define PPTOT 8192
#define NTHREADS 128
#define XCHUNKS 16                  // PPTOT / (NTHREADS*4)
#define ZSPLIT 4
#define NTILES (XCHUNKS * ZSPLIT)   // 64 partial slots per batch
#define TOTBLK (XCHUNKS * BB * ZSPLIT)  // 1024 blocks = 1 wave @ 7 blocks/SM

__device__ float g_part[BB][4][NTILES];
__device__ unsigned int g_cnt = 0;

typedef unsigned long long f2;

__device__ __forceinline__ float rsqrt_a(float x) { float y; asm("rsqrt.approx.f32 %0,%1;" : "=f"(y) : "f"(x)); return y; }
__device__ __forceinline__ float sqrt_a(float x)  { float y; asm("sqrt.approx.f32 %0,%1;"  : "=f"(y) : "f"(x)); return y; }
__device__ __forceinline__ float rcp_a(float x)   { float y; asm("rcp.approx.f32 %0,%1;"   : "=f"(y) : "f"(x)); return y; }
__device__ __forceinline__ float tanh_a(float x)  { float y; asm("tanh.approx.f32 %0,%1;"  : "=f"(y) : "f"(x)); return y; }

__device__ __forceinline__ f2 pk(float lo, float hi) { f2 r; asm("mov.b64 %0,{%1,%2};" : "=l"(r) : "f"(lo), "f"(hi)); return r; }
__device__ __forceinline__ void upk(f2 v, float& lo, float& hi) { asm("mov.b64 {%0,%1},%2;" : "=f"(lo), "=f"(hi) : "l"(v)); }
__device__ __forceinline__ f2 fma2(f2 a, f2 b, f2 c) { f2 r; asm("fma.rn.f32x2 %0,%1,%2,%3;" : "=l"(r) : "l"(a), "l"(b), "l"(c)); return r; }
__device__ __forceinline__ f2 mul2(f2 a, f2 b) { f2 r; asm("mul.rn.f32x2 %0,%1,%2;" : "=l"(r) : "l"(a), "l"(b)); return r; }
__device__ __forceinline__ f2 add2(f2 a, f2 b) { f2 r; asm("add.rn.f32x2 %0,%1,%2;" : "=l"(r) : "l"(a), "l"(b)); return r; }

__global__ void __launch_bounds__(NTHREADS, 7) pair_kernel(
    const float* __restrict__ posL, const float* __restrict__ posP,
    const float* __restrict__ qL,   const float* __restrict__ qP,
    const float* __restrict__ xL,   const float* __restrict__ xP,
    const float* __restrict__ vdw,  const float* __restrict__ epst,
    float* __restrict__ out)
{
    // Ligand scalars, pre-duplicated; each row = 4 x 16B so LDS.128 yields 2 packed
    // operands per load. [l]: (-2x)(-2y)(-2z)(|pL|^2+1e-8)(83q)(sqrt2*rl)(se)(x0)
    __shared__ __align__(16) float2 sL[LQ][8];
    __shared__ float  red[4][4];
    __shared__ int    s_last;

    const int b   = blockIdx.y;
    const int tid = threadIdx.x;
    const int lbase = blockIdx.z * LQ;

    if (tid < LQ) {
        const int l = lbase + tid;
        const float* xl = xL + ((size_t)b * LTOT + l) * 9;
        float rl = 0.0f, el = 0.0f;
#pragma unroll
        for (int i = 0; i < 9; i++) {
            float v = xl[i];
            rl = fmaf(v, vdw[i],  rl);
            el = fmaf(v, epst[i], el);
        }
        el = fmaxf(el, 0.0f);
        const float* pl = posL + ((size_t)b * LTOT + l) * 3;
        float lx = pl[0], ly = pl[1], lz = pl[2];
        float sq = fmaf(lx, lx, fmaf(ly, ly, fmaf(lz, lz, 1e-8f)));
        float aw = 83.015f * qL[b * LTOT + l];
        float se = sqrt_a(el);
        float rls = 1.41421356237309515f * rl;   // sqrt(2)*radii_L
        sL[tid][0] = make_float2(-2.0f * lx, -2.0f * lx);
        sL[tid][1] = make_float2(-2.0f * ly, -2.0f * ly);
        sL[tid][2] = make_float2(-2.0f * lz, -2.0f * lz);
        sL[tid][3] = make_float2(sq, sq);
        sL[tid][4] = make_float2(aw, aw);
        sL[tid][5] = make_float2(rls, rls);
        sL[tid][6] = make_float2(se, se);
        sL[tid][7] = make_float2(xl[0], xl[0]);
    }
    __syncthreads();

    // --- per-thread protein atoms: 4, as two packed sets ---
    f2 ppx[2], ppy[2], ppz[2], sqp[2], qp2[2], rp2[2], sep64[2], x0p2[2];
#pragma unroll
    for (int s = 0; s < 2; s++) {
        const int p0 = blockIdx.x * (NTHREADS * 4) + s * (NTHREADS * 2) + tid;
        const int p1 = p0 + NTHREADS;
        const size_t b0 = (size_t)b * PPTOT + p0;
        const size_t b1 = (size_t)b * PPTOT + p1;
        const float* pp0 = posP + b0 * 3;
        const float* pp1 = posP + b1 * 3;
        float x0c = pp0[0], y0c = pp0[1], z0c = pp0[2];
        float x1c = pp1[0], y1c = pp1[1], z1c = pp1[2];
        ppx[s] = pk(x0c, x1c);
        ppy[s] = pk(y0c, y1c);
        ppz[s] = pk(z0c, z1c);
        sqp[s] = pk(fmaf(x0c, x0c, fmaf(y0c, y0c, z0c * z0c)),
                    fmaf(x1c, x1c, fmaf(y1c, y1c, z1c * z1c)));
        qp2[s] = pk(qP[b0], qP[b1]);
        const float* xp0 = xP + b0 * 4;
        const float* xp1 = xP + b1 * 4;
        float r0 = fmaf(xp0[0], 1.7f, fmaf(xp0[1], 1.55f, fmaf(xp0[2], 1.52f, xp0[3] * 1.8f)));
        float r1 = fmaf(xp1[0], 1.7f, fmaf(xp1[1], 1.55f, fmaf(xp1[2], 1.52f, xp1[3] * 1.8f)));
        float e0 = fmaf(xp0[0], 0.1f, fmaf(xp0[1], 0.1f, fmaf(xp0[2], 0.15f, xp0[3] * 0.2f)));
        float e1 = fmaf(xp1[0], 0.1f, fmaf(xp1[1], 0.1f, fmaf(xp1[2], 0.15f, xp1[3] * 0.2f)));
        rp2[s]   = pk(1.41421356237309515f * r0, 1.41421356237309515f * r1);  // sqrt(2)*radii_P
        // ce/64 = se_L * (4*sqrt(eps_P)/64) = se_L * 0.0625*sqrt(eps_P)
        sep64[s] = pk(0.0625f * sqrt_a(e0), 0.0625f * sqrt_a(e1));
        x0p2[s]  = pk(xp0[0], xp1[0]);
    }

    // packed constants (tanh cubic: ee = eer + eer^3*C_U1)
    const f2 C_U1   = pk(-8.3333333e-6f, -8.3333333e-6f);
    const f2 C_NEG8 = pk(-8.0f, -8.0f);
    const f2 C_HALF = pk(0.5f, 0.5f);
    const f2 C_256  = pk(256.0f, 256.0f);

    f2 acc_l = 0ull, acc_d = 0ull;
    f2 acc_h[2] = {0ull, 0ull};
    float accp0 = 0.0f, accp1 = 0.0f;

#pragma unroll 8
    for (int l = 0; l < LQ; l++) {
        const ulonglong2* slv = (const ulonglong2*)sL[l];
        ulonglong2 v01 = slv[0];   // (-2x) (-2y)
        ulonglong2 v23 = slv[1];   // (-2z) (sql)
        ulonglong2 v45 = slv[2];   // (aw)  (sqrt2*rl)
        ulonglong2 v67 = slv[3];   // (se)  (x0)

#pragma unroll
        for (int s = 0; s < 2; s++) {
            // d2 = |pL|^2 + |pP|^2 - 2 pL.pP  (+1e-8 folded into sql)
            f2 ssum = add2(v23.y, sqp[s]);
            f2 d2 = fma2(v01.x, ppx[s], fma2(v01.y, ppy[s], fma2(v23.x, ppz[s], ssum)));
            f2 sig_s = add2(v45.y, rp2[s]);          // sqrt(2)*sigma
            f2 s2    = fma2(sig_s, sig_s, d2);        // d2 + 2*sigma^2
            float s2l, s2h; upk(s2, s2l, s2h);
            f2 isd = pk(rsqrt_a(s2l), rsqrt_a(s2h)); // 1/soft_dist

            // hsa reciprocal, independent of sqrt chain: rcph = 1/(d2^2 + 256)
            f2 hd = fma2(d2, d2, C_256);
            float hdl, hdh; upk(hd, hdl, hdh);
            f2 rcph = pk(rcp_a(hdl), rcp_a(hdh));

            // dist + mask via tanh: mask = 0.5 + 0.5*tanh(12 - d)
            float d2l, d2h; upk(d2, d2l, d2h);
            float dl = sqrt_a(d2l), dh = sqrt_a(d2h);
            float thl = tanh_a(12.0f - dl);
            float thh = tanh_a(12.0f - dh);
            f2 mask = fma2(pk(thl, thh), C_HALF, C_HALF);

            // e_elec = 200*tanh(eer/200): ee = eer + eer^3*c1 (cubic)
            f2 eer = mul2(mul2(v45.x, qp2[s]), isd);
            f2 u   = mul2(eer, eer);
            f2 m   = mul2(eer, u);
            f2 ee  = fma2(m, C_U1, eer);

            // LJ soft-core with sqrt2-scaled ratio: rs6 = (sqrt2*ratio)^6 <= 1
            // evr = (ce/64) * rs6 * (rs6 - 8)  ==  4*eps*(ratio^12 - ratio^6)
            f2 rat = mul2(sig_s, isd);
            f2 r2 = mul2(rat, rat);
            f2 rs6 = mul2(mul2(r2, r2), r2);
            f2 ce = mul2(v67.x, sep64[s]);
            f2 evr = mul2(mul2(ce, rs6), add2(rs6, C_NEG8));
            f2 e3  = mul2(mul2(evr, evr), evr);
            f2 suml = add2(ee, evr);                   // log branch (clamp = identity)

            // accumulate
            f2 rhm = mul2(rcph, mask);                 // = mask/(d^4+256); x256 in epilogue
            acc_h[s] = fma2(v67.y, rhm, acc_h[s]);     // x0p factored out post-loop
            acc_l = fma2(suml, mask, acc_l);
            acc_d = fma2(e3, mask, acc_d);             // soft = log - acc_d/300

            // pauli: overlap = max(0.6*sigma - d, 0) = max(0.424264*sig_s - d, 0)
            float sgl, sgh; upk(sig_s, sgl, sgh);
            float ov0 = fmaxf(fmaf(sgl, 0.42426406871192851f, -dl), 0.0f);
            float ov1 = fmaxf(fmaf(sgh, 0.42426406871192851f, -dh), 0.0f);
            accp0 = fmaf(ov0, ov0, accp0);
            accp1 = fmaf(ov1, ov1, accp1);
        }
    }

    acc_h[0] = mul2(acc_h[0], x0p2[0]);   // deferred x_P[0] factors
    acc_h[1] = mul2(acc_h[1], x0p2[1]);

    // --- block reduction ---
    float v1l, v1h, vdl, vdh, h0l, h0h, h1l, h1h;
    upk(acc_l, v1l, v1h);
    upk(acc_d, vdl, vdh);
    upk(acc_h[0], h0l, h0h);
    upk(acc_h[1], h1l, h1h);
    float v1 = v1l + v1h;
    float v0 = fmaf(vdl + vdh, -3.3333333333e-3f, v1);   // soft sum
    float v2 = (h0l + h0h) + (h1l + h1h);
    float v3 = accp0 + accp1;
#pragma unroll
    for (int off = 16; off > 0; off >>= 1) {
        v0 += __shfl_xor_sync(0xFFFFFFFFu, v0, off);
        v1 += __shfl_xor_sync(0xFFFFFFFFu, v1, off);
        v2 += __shfl_xor_sync(0xFFFFFFFFu, v2, off);
        v3 += __shfl_xor_sync(0xFFFFFFFFu, v3, off);
    }
    const int wid = tid >> 5;
    if ((tid & 31) == 0) {
        red[wid][0] = v0; red[wid][1] = v1; red[wid][2] = v2; red[wid][3] = v3;
    }
    __syncthreads();
    const int slot = blockIdx.z * XCHUNKS + blockIdx.x;
    if (tid < 4) {
        float s = red[0][tid] + red[1][tid] + red[2][tid] + red[3][tid];
        g_part[b][tid][slot] = s;
    }
    __threadfence();
    if (tid == 0) {
        unsigned int old = atomicAdd(&g_cnt, 1u);
        s_last = (old == TOTBLK - 1) ? 1 : 0;
    }
    __syncthreads();
    if (!s_last) return;

    // --- last block: final reduction + epilogue ---
    __threadfence();
    __shared__ float fin[BB][4];
    {
        const int slot2 = tid >> 1;           // 0..63  (16 batches x 4 comps)
        const int half  = tid & 1;
        const int fb = slot2 >> 2, fc = slot2 & 3;
        float s = 0.0f;
#pragma unroll 8
        for (int i = half * (NTILES / 2); i < (half + 1) * (NTILES / 2); i++)
            s += g_part[fb][fc][i];
        s += __shfl_xor_sync(0xFFFFFFFFu, s, 1);
        if (half == 0) fin[fb][fc] = s;
    }
    __syncthreads();
    if (tid < BB) {
        float s  = fin[tid][0];
        float lg = fin[tid][1];
        float h  = fin[tid][2];
        float pa = fin[tid][3];

        float e_hsa   = -0.5f * 256.0f * h;
        float e_pauli = 95.257412682243336f * pa;   // sigmoid(3.0)*100

        float e_raw  = s + 5.0f * e_hsa + e_pauli;
        float e_hard = fminf(e_pauli, 10000.0f);
        float e_soft_log = fminf(fmaxf(lg + 5.0f * e_hsa, -500.0f), 5000.0f);
        float loge = fminf(e_soft_log + e_hard, 1000000.0f);

        out[tid]      = e_raw;
        out[16 + tid] = e_hard;
        out[33 + tid] = loge;
    }
    if (tid == 0) {
        out[32] = 2.0f;   // ALPHA
        g_cnt = 0;        // reset for next graph replay (deterministic)
    }
}

extern "C" void kernel_launch(void* const* d_in, const int* in_sizes, int n_in,
                              void* d_out, int out_size) {
    const float* posL = (const float*)d_in[0];
    const float* posP = (const float*)d_in[1];
    const float* qL   = (const float*)d_in[2];
    const float* qP   = (const float*)d_in[3];
    const float* xL   = (const float*)d_in[4];
    const float* xP   = (const float*)d_in[5];
    const float* vdw  = (const float*)d_in[6];
    const float* epst = (const float*)d_in[7];
    float* out = (float*)d_out;

    dim3 grid(XCHUNKS, BB, ZSPLIT);
    pair_kernel<<<grid, NTHREADS>>>(posL, posP, qL, qP, xL, xP, vdw, epst, out);
}